// round 13
// baseline (speedup 1.0000x reference)
#include <cuda_runtime.h>
#include <cuda_bf16.h>

#define NB 8
#define NPTS 16384
#define NQ 1024
#define NC 64
#define NS 32
#define R2 0.04f

// 2 MB scratch: xyz packed as float4 for single-LDG.128 scan loads.
__device__ float4 g_xyz4[(size_t)NB * NPTS];
// 33.5 MB scratch: features transposed to (B, N, C); fits in L2 (126 MB).
__device__ float g_feats_t[(size_t)NB * NPTS * NC];

#define TBLOCKS (NB * (NPTS / 32))      // 4096 transpose tiles
#define PBLOCKS ((NB * NPTS) / 256)     // 512 pack blocks

// ---- fused pre-pass: feats transpose + xyz pack (job by blockIdx.x) ----
__global__ __launch_bounds__(256) void prepass_kernel(
    const float* __restrict__ xyz, const float* __restrict__ feats)
{
    if (blockIdx.x < TBLOCKS) {
        __shared__ float tile[32][65];
        const int b  = blockIdx.x >> 9;          // / (NPTS/32)
        const int n0 = (blockIdx.x & 511) * 32;
        const int t  = threadIdx.x;
        const int tx = t & 31;
        const int ty = t >> 5;

        const float* src = feats + (size_t)b * NC * NPTS + n0;
        #pragma unroll
        for (int k = 0; k < 8; ++k) {
            const int c = ty * 8 + k;
            tile[tx][c] = src[(size_t)c * NPTS + tx];
        }
        __syncthreads();

        float* dst = g_feats_t + ((size_t)b * NPTS + n0) * NC;
        #pragma unroll
        for (int k = 0; k < 8; ++k) {
            const int idx = k * 256 + t;
            const int n = idx >> 6;
            const int c = idx & 63;
            dst[(size_t)n * NC + c] = tile[n][c];
        }
    } else {
        __shared__ float sbuf[8][96];
        const int bid  = blockIdx.x - TBLOCKS;
        const int warp = threadIdx.x >> 5, lane = threadIdx.x & 31;
        const size_t base = (size_t)bid * 256 + warp * 32;
        const float* src = xyz + base * 3;
        float* s = sbuf[warp];
        s[lane]      = src[lane];
        s[lane + 32] = src[lane + 32];
        s[lane + 64] = src[lane + 64];
        __syncwarp();
        g_xyz4[base + lane] = make_float4(s[lane * 3], s[lane * 3 + 1], s[lane * 3 + 2], 0.f);
    }
}

#define FSTRIDE 68   // fsm row stride in floats: conflict-free STS.128/LDS.128

// ---- main: one block (8 warps) per query; 2048 points per round ----
__global__ __launch_bounds__(256) void qag_kernel(
    const float* __restrict__ new_xyz,  // (B, S, 3)
    float* __restrict__ out)            // (B, 3+C, S, NS)
{
    const int lane = threadIdx.x & 31;
    const int w    = threadIdx.x >> 5;         // warp id 0..7
    const int q = blockIdx.x;                  // one query per block
    const int b = q >> 10;                     // / NQ
    const int s = q & (NQ - 1);

    // 31 carried + up to 2048 appended in the crossing round: unchecked stores.
    __shared__ int   idx_buf[NS + 2048];
    __shared__ int   wtot[2][8];               // double-buffered per-warp counts
    __shared__ float fsm[NS * FSTRIDE];        // [sample][channel]

    const float qx = new_xyz[q * 3 + 0];
    const float qy = new_xyz[q * 3 + 1];
    const float qz = new_xyz[q * 3 + 2];

    const float4* __restrict__ xb4 = g_xyz4 + (size_t)b * NPTS;
    const unsigned lt = (1u << lane) - 1u;

    // ---- ball query: 2048-pt rounds, warp w owns sub-chunk [w*256, +256) ----
    int cnt = 0;
    int pb = 0;
    for (int j0 = 0; j0 < NPTS; j0 += 2048) {
        const int jw = j0 + w * 256;
        float4 p[8];
        #pragma unroll
        for (int u = 0; u < 8; ++u) p[u] = xb4[jw + u * 32 + lane];

        bool wi[8];
        #pragma unroll
        for (int u = 0; u < 8; ++u) {
            const float dx = p[u].x - qx;
            const float dy = p[u].y - qy;
            const float dz = p[u].z - qz;
            wi[u] = dx * dx + dy * dy + dz * dz < R2;
        }
        unsigned m[8];
        #pragma unroll
        for (int u = 0; u < 8; ++u) m[u] = __ballot_sync(0xFFFFFFFFu, wi[u]);

        int tot = 0;
        #pragma unroll
        for (int u = 0; u < 8; ++u) tot += __popc(m[u]);
        if (lane == 0) wtot[pb][w] = tot;
        __syncthreads();

        // warp's write base = carried count + counts of lower warps this round
        int base = cnt;
        #pragma unroll
        for (int ww = 0; ww < 8; ++ww) {
            const int t = wtot[pb][ww];
            if (ww < w) base += t;
            cnt += t;
        }
        #pragma unroll
        for (int u = 0; u < 8; ++u) {
            if (wi[u]) idx_buf[base + __popc(m[u] & lt)] = jw + u * 32 + lane;
            base += __popc(m[u]);
        }
        pb ^= 1;                // next round uses the other wtot buffer
        if (cnt >= NS) break;   // uniform across block
    }
    __syncthreads();            // idx_buf (final round) visible to all warps

    const int eff = cnt < NS ? cnt : NS;
    const int first = (eff > 0) ? idx_buf[0] : 0;   // pad value, inline

    const size_t CH = (size_t)NQ * NS;              // channel stride
    float* ob = out + ((size_t)b * (3 + NC) * NQ + s) * NS + lane;

    // ---- grouped xyz (warp 0 only), coalesced writes ----
    if (w == 0) {
        const int im = (lane < eff) ? idx_buf[lane] : first;
        const float4 P = xb4[im];
        ob[0 * CH] = P.x - qx;
        ob[1 * CH] = P.y - qy;
        ob[2 * CH] = P.z - qz;
    }

    // ---- grouped features: half-warp per sample row -> fsm via STS.128 ----
    // warp w loads samples 4w..4w+3; lane g=lane&15 owns float4 group g.
    {
        const float4* __restrict__ fbase = (const float4*)(g_feats_t + (size_t)b * NPTS * NC);
        const int g    = lane & 15;
        const int half = lane >> 4;
        #pragma unroll
        for (int i = 0; i < 2; ++i) {
            const int msamp = 4 * w + 2 * i + half;
            const int im = (msamp < eff) ? idx_buf[msamp] : first;
            const float4 v = __ldg(fbase + (size_t)im * (NC / 4) + g);
            *(float4*)&fsm[msamp * FSTRIDE + 4 * g] = v;   // STS.128, conflict-free
        }
    }
    __syncthreads();

    // ---- writeout: warp w covers channels 8w..8w+7 via LDS.128, lane = sample ----
    float* of = ob + 3 * CH;
    #pragma unroll
    for (int c4 = 0; c4 < 2; ++c4) {
        const int ch0 = 8 * w + 4 * c4;
        const float4 fv = *(const float4*)&fsm[lane * FSTRIDE + ch0];  // LDS.128
        of[(size_t)(ch0 + 0) * CH] = fv.x;
        of[(size_t)(ch0 + 1) * CH] = fv.y;
        of[(size_t)(ch0 + 2) * CH] = fv.z;
        of[(size_t)(ch0 + 3) * CH] = fv.w;
    }
}

extern "C" void kernel_launch(void* const* d_in, const int* in_sizes, int n_in,
                              void* d_out, int out_size) {
    const float* xyz     = (const float*)d_in[0];
    const float* new_xyz = (const float*)d_in[1];
    const float* feats   = (const float*)d_in[2];
    float* out = (float*)d_out;

    prepass_kernel<<<TBLOCKS + PBLOCKS, 256>>>(xyz, feats);

    qag_kernel<<<NB * NQ, 256>>>(new_xyz, out);   // one block (8 warps) per query
}

// round 15
// speedup vs baseline: 1.4873x; 1.4873x over previous
#include <cuda_runtime.h>
#include <cuda_bf16.h>

#define NB 8
#define NPTS 16384
#define NQ 1024
#define NC 64
#define NS 32
#define R2 0.04f

// 2 MB scratch: xyz packed as float4 for single-LDG.128 scan loads.
__device__ float4 g_xyz4[(size_t)NB * NPTS];
// 33.5 MB scratch: features transposed to (B, N, C); fits in L2 (126 MB).
__device__ float g_feats_t[(size_t)NB * NPTS * NC];
// work-stealing counter for the persistent qag kernel
__device__ int g_qctr;

#define TBLOCKS (NB * (NPTS / 32))      // 4096 transpose tiles
#define PBLOCKS ((NB * NPTS) / 256)     // 512 pack blocks
#define NQTOT   (NB * NQ)               // 8192 queries
#define QAG_GRID 1776                   // 148 SMs x 12 resident blocks

// ---- fused pre-pass: feats transpose + xyz pack + counter reset ----
__global__ __launch_bounds__(256) void prepass_kernel(
    const float* __restrict__ xyz, const float* __restrict__ feats)
{
    if (blockIdx.x == 0 && threadIdx.x == 0) g_qctr = 0;  // reset for qag (same stream)

    if (blockIdx.x < TBLOCKS) {
        __shared__ float tile[32][65];
        const int b  = blockIdx.x >> 9;          // / (NPTS/32)
        const int n0 = (blockIdx.x & 511) * 32;
        const int t  = threadIdx.x;
        const int tx = t & 31;
        const int ty = t >> 5;

        const float* src = feats + (size_t)b * NC * NPTS + n0;
        #pragma unroll
        for (int k = 0; k < 8; ++k) {
            const int c = ty * 8 + k;
            tile[tx][c] = src[(size_t)c * NPTS + tx];
        }
        __syncthreads();

        float* dst = g_feats_t + ((size_t)b * NPTS + n0) * NC;
        #pragma unroll
        for (int k = 0; k < 8; ++k) {
            const int idx = k * 256 + t;
            const int n = idx >> 6;
            const int c = idx & 63;
            dst[(size_t)n * NC + c] = tile[n][c];
        }
    } else {
        __shared__ float sbuf[8][96];
        const int bid  = blockIdx.x - TBLOCKS;
        const int warp = threadIdx.x >> 5, lane = threadIdx.x & 31;
        const size_t base = (size_t)bid * 256 + warp * 32;
        const float* src = xyz + base * 3;
        float* s = sbuf[warp];
        s[lane]      = src[lane];
        s[lane + 32] = src[lane + 32];
        s[lane + 64] = src[lane + 64];
        __syncwarp();
        g_xyz4[base + lane] = make_float4(s[lane * 3], s[lane * 3 + 1], s[lane * 3 + 2], 0.f);
    }
}

#define FSTRIDE 68   // fsm row stride in floats: conflict-free STS.128/LDS.128

// ---- main: persistent blocks (4 warps) stealing queries; R8 body per query ----
__global__ __launch_bounds__(128) void qag_kernel(
    const float* __restrict__ new_xyz,  // (B, S, 3)
    float* __restrict__ out)            // (B, 3+C, S, NS)
{
    const int lane = threadIdx.x & 31;
    const int w    = threadIdx.x >> 5;         // warp id 0..3

    // fsm MUST be 16B-aligned for STS.128/LDS.128 (R13 crash: it wasn't).
    __shared__ __align__(16) float fsm[NS * FSTRIDE];  // [sample][channel]
    __shared__ __align__(16) int   idx_buf[NS + 1024]; // 31 carried + <=1024 appended
    __shared__ int   wtot[2][4];               // double-buffered per-warp counts
    __shared__ int   cur_q;

    const unsigned lt = (1u << lane) - 1u;

    for (;;) {
        if (threadIdx.x == 0) cur_q = atomicAdd(&g_qctr, 1);
        __syncthreads();
        const int q = cur_q;
        if (q >= NQTOT) break;                 // uniform across block

        const int b = q >> 10;                 // / NQ
        const int s = q & (NQ - 1);

        const float qx = new_xyz[q * 3 + 0];
        const float qy = new_xyz[q * 3 + 1];
        const float qz = new_xyz[q * 3 + 2];

        const float4* __restrict__ xb4 = g_xyz4 + (size_t)b * NPTS;

        // ---- ball query: 1024-pt rounds, warp w owns sub-chunk [w*256, +256) ----
        int cnt = 0;
        int pb = 0;
        for (int j0 = 0; j0 < NPTS; j0 += 1024) {
            const int jw = j0 + w * 256;
            float4 p[8];
            #pragma unroll
            for (int u = 0; u < 8; ++u) p[u] = xb4[jw + u * 32 + lane];

            bool wi[8];
            #pragma unroll
            for (int u = 0; u < 8; ++u) {
                const float dx = p[u].x - qx;
                const float dy = p[u].y - qy;
                const float dz = p[u].z - qz;
                wi[u] = dx * dx + dy * dy + dz * dz < R2;
            }
            unsigned m[8];
            #pragma unroll
            for (int u = 0; u < 8; ++u) m[u] = __ballot_sync(0xFFFFFFFFu, wi[u]);

            int tot = 0;
            #pragma unroll
            for (int u = 0; u < 8; ++u) tot += __popc(m[u]);
            if (lane == 0) wtot[pb][w] = tot;
            __syncthreads();

            int base = cnt;
            #pragma unroll
            for (int ww = 0; ww < 4; ++ww) {
                const int t = wtot[pb][ww];
                if (ww < w) base += t;
                cnt += t;
            }
            #pragma unroll
            for (int u = 0; u < 8; ++u) {
                if (wi[u]) idx_buf[base + __popc(m[u] & lt)] = jw + u * 32 + lane;
                base += __popc(m[u]);
            }
            pb ^= 1;
            if (cnt >= NS) break;   // uniform across block
        }
        __syncthreads();            // final-round idx_buf visible

        const int eff = cnt < NS ? cnt : NS;
        const int first = (eff > 0) ? idx_buf[0] : 0;

        const size_t CH = (size_t)NQ * NS;
        float* ob = out + ((size_t)b * (3 + NC) * NQ + s) * NS + lane;

        // ---- grouped xyz (warp 0 only), coalesced writes ----
        if (w == 0) {
            const int im = (lane < eff) ? idx_buf[lane] : first;
            const float4 P = xb4[im];
            ob[0 * CH] = P.x - qx;
            ob[1 * CH] = P.y - qy;
            ob[2 * CH] = P.z - qz;
        }

        // ---- grouped features: half-warp per sample row -> fsm via STS.128 ----
        {
            const float4* __restrict__ fbase =
                (const float4*)(g_feats_t + (size_t)b * NPTS * NC);
            const int g    = lane & 15;
            const int half = lane >> 4;
            #pragma unroll
            for (int i = 0; i < 4; ++i) {
                const int msamp = 8 * w + 2 * i + half;
                const int im = (msamp < eff) ? idx_buf[msamp] : first;
                const float4 v = __ldg(fbase + (size_t)im * (NC / 4) + g);
                *(float4*)&fsm[msamp * FSTRIDE + 4 * g] = v;   // STS.128
            }
        }
        __syncthreads();

        // ---- writeout: warp w covers channels 16w..16w+15 via LDS.128 ----
        float* of = ob + 3 * CH;
        #pragma unroll
        for (int c4 = 0; c4 < 4; ++c4) {
            const int ch0 = 16 * w + 4 * c4;
            const float4 fv = *(const float4*)&fsm[lane * FSTRIDE + ch0];
            of[(size_t)(ch0 + 0) * CH] = fv.x;
            of[(size_t)(ch0 + 1) * CH] = fv.y;
            of[(size_t)(ch0 + 2) * CH] = fv.z;
            of[(size_t)(ch0 + 3) * CH] = fv.w;
        }
        __syncthreads();            // protect smem reuse next iteration
    }
}

extern "C" void kernel_launch(void* const* d_in, const int* in_sizes, int n_in,
                              void* d_out, int out_size) {
    const float* xyz     = (const float*)d_in[0];
    const float* new_xyz = (const float*)d_in[1];
    const float* feats   = (const float*)d_in[2];
    float* out = (float*)d_out;

    prepass_kernel<<<TBLOCKS + PBLOCKS, 256>>>(xyz, feats);

    qag_kernel<<<QAG_GRID, 128>>>(new_xyz, out);   // persistent, work-stealing
}